// round 6
// baseline (speedup 1.0000x reference)
#include <cuda_runtime.h>
#include <cstdint>
#include <math.h>

// ---------------- static device scratch (no allocation allowed) ----------------
#define MAXM 25088          // 256*98
__device__ float g_xa[MAXM * 512];
__device__ float g_xb[MAXM * 512];
__device__ float g_at[MAXM * 512];
__device__ float g_tp[MAXM * 512];
__device__ float g_qk[MAXM * 1536];
__device__ float g_hd[MAXM * 1024];
__device__ float g_qkvT[2 * 1536 * 512];   // [l][n][k]
__device__ float g_woT[2 * 512 * 512];
__device__ float g_w1T[2 * 1024 * 512];
__device__ float g_w2T[2 * 512 * 1024];
__device__ float g_cvT[2 * 512 * 1536];    // conv weights as BT [l][o][tap*512+i]
__device__ float g_cn[8192];               // ||c||^2
__device__ unsigned long long g_key[12544];

__device__ __forceinline__ float gelu_f(float x) {
    return 0.5f * x * (1.0f + erff(x * 0.7071067811865476f));
}

__device__ __forceinline__ uint32_t tf32_of(float x) {
    uint32_t r;
    asm("cvt.rna.tf32.f32 %0, %1;" : "=r"(r) : "f"(x));
    return r;
}

#define MMA_TF32(d, a0, a1, a2, a3, b0, b1)                                      \
    asm volatile("mma.sync.aligned.m16n8k8.row.col.f32.tf32.tf32.f32 "           \
                 "{%0,%1,%2,%3}, {%4,%5,%6,%7}, {%8,%9}, {%0,%1,%2,%3};"         \
                 : "+f"((d)[0]), "+f"((d)[1]), "+f"((d)[2]), "+f"((d)[3])        \
                 : "r"(a0), "r"(a1), "r"(a2), "r"(a3), "r"(b0), "r"(b1))

// ---------------- weight prep ----------------
__global__ void tr_w(const float* __restrict__ src, float* __restrict__ dst, int K, int N) {
    __shared__ float t[32][33];
    int n0 = blockIdx.x * 32, k0 = blockIdx.y * 32;
    int tx = threadIdx.x, ty = threadIdx.y;
    for (int i = ty; i < 32; i += 8) t[i][tx] = src[(size_t)(k0 + i) * N + n0 + tx];
    __syncthreads();
    for (int i = ty; i < 32; i += 8) dst[(size_t)(n0 + i) * K + k0 + tx] = t[tx][i];
}

__global__ void tr_conv(const float* __restrict__ w, float* __restrict__ dst) {
    int id = blockIdx.x * 256 + threadIdx.x;
    if (id >= 2 * 512 * 1536) return;
    int l = id / (512 * 1536);
    int rem = id % (512 * 1536);
    int o = rem / 1536;
    int kk = rem % 1536;
    int tap = kk / 512, i = kk & 511;
    dst[id] = w[(((size_t)l * 512 + o) * 512 + i) * 3 + tap];
}

__global__ void cnorm_k(const float* __restrict__ cb, float* __restrict__ cn) {
    int warp = threadIdx.x >> 5, lane = threadIdx.x & 31;
    int row = blockIdx.x * 8 + warp;
    const float* rp = cb + (size_t)row * 512;
    float s = 0.f;
#pragma unroll
    for (int c = 0; c < 4; c++) {
        float4 v = *(const float4*)(rp + lane * 4 + c * 128);
        s += v.x * v.x + v.y * v.y + v.z * v.z + v.w * v.w;
    }
#pragma unroll
    for (int o = 16; o; o >>= 1) s += __shfl_xor_sync(0xffffffffu, s, o);
    if (!lane) cn[row] = s;
}

__global__ void key_init(unsigned long long* k) {
    int i = blockIdx.x * 256 + threadIdx.x;
    if (i < 12544) k[i] = ~0ull;
}

// ---------------- 3xTF32 mma.sync GEMM: 128x128 block, 512 thr, 32x32/warp ----------------
// C[M,N] = A[M,Kd] @ BT[N,Kd]^T + epilogue
// EPI: 0 +bias | 1 +bias,relu | 2 +bias,gelu | 3 +bias+res | 4 VQ argmin (bias = ||c||^2)
// smem float4 layout per tile: idx = kstep*522 + c*130 + row  (c = k%4 of an 8-k step)
//   cell = (hi[k=c], hi[k=c+4], lo[k=c], lo[k=c+4])
static constexpr int TILE_F4 = 1044;            // one operand tile
static constexpr int BUF_F4  = 2 * TILE_F4;     // A + B
static constexpr int SMEM_MMA = 2 * BUF_F4 * 16 + 1024;  // 66816 + red table

template<int EPI, bool GATHER>
__global__ __launch_bounds__(512, 1)
void gemm_mma(const float* __restrict__ A, const float* __restrict__ BT,
              const float* __restrict__ bias, const float* __restrict__ res,
              float* __restrict__ C, unsigned long long* __restrict__ keys,
              int M, int N, int Kd, int Tin, int Tout)
{
    extern __shared__ float4 sm4[];
    unsigned long long* red = (unsigned long long*)(sm4 + 2 * BUF_F4);
    const int tid = threadIdx.x, lane = tid & 31, wid = tid >> 5;
    const int wr = wid >> 2, wc = wid & 3;
    const int row0 = blockIdx.y * 128, col0 = blockIdx.x * 128;

    if (EPI == 4 && tid < 128) red[tid] = ~0ull;

    // loaders: tid<256 -> A (row lrow), else B (row lrow of BT); kb = k-step half
    const bool isA = tid < 256;
    const int lrow = (tid & 255) >> 1;
    const int kb = tid & 1;
    int gbase = 0, t2 = 0;
    const float* gp0;
    if (isA) {
        if (GATHER) {
            int r = row0 + lrow;
            int b2 = r / Tout;
            int t = r - b2 * Tout;
            gbase = b2 * Tin;
            t2 = 2 * t - 2;
            gp0 = A;
        } else {
            gp0 = A + (size_t)(row0 + lrow) * Kd + kb * 8;
        }
    } else {
        gp0 = BT + (size_t)(col0 + lrow) * Kd + kb * 8;
    }

    auto ldg8 = [&](int c, float4& u, float4& v) {
        const float* p;
        if (GATHER && isA) {
            int k0 = c * 16;
            int tap = k0 >> 9;
            int fr = t2 + tap;
            if (fr < 0) fr = 0;
            p = gp0 + (((size_t)(gbase + fr)) << 9) + (k0 & 511) + kb * 8;
        } else {
            p = gp0 + c * 16;
        }
        u = *(const float4*)p;
        v = *(const float4*)(p + 4);
    };
    auto sts = [&](int buf, float4 u, float4 v) {
        float f[8] = {u.x, u.y, u.z, u.w, v.x, v.y, v.z, v.w};
        uint32_t hi[8], lo[8];
#pragma unroll
        for (int e = 0; e < 8; e++) {
            hi[e] = tf32_of(f[e]);
            lo[e] = tf32_of(f[e] - __uint_as_float(hi[e]));
        }
        float4* base = sm4 + buf * BUF_F4 + (isA ? 0 : TILE_F4) + kb * 522 + lrow;
#pragma unroll
        for (int cc = 0; cc < 4; cc++) {
            uint4 val = make_uint4(hi[cc], hi[cc + 4], lo[cc], lo[cc + 4]);
            *(uint4*)(base + cc * 130) = val;
        }
    };

    float acc[2][4][4];
#pragma unroll
    for (int mt = 0; mt < 2; mt++)
#pragma unroll
        for (int nt = 0; nt < 4; nt++)
#pragma unroll
            for (int e = 0; e < 4; e++) acc[mt][nt][e] = 0.f;

    float4 u, v;
    ldg8(0, u, v);
    sts(0, u, v);
    __syncthreads();

    const int nC = Kd >> 4;
    const int aoff = (lane & 3) * 130 + (lane >> 2);
    for (int c = 0; c < nC; c++) {
        int cur = c & 1;
        float4 u2, v2;
        if (c + 1 < nC) ldg8(c + 1, u2, v2);
        const float4* Ab = sm4 + cur * BUF_F4;
        const float4* Bb = Ab + TILE_F4;
#pragma unroll
        for (int ks = 0; ks < 2; ks++) {
            uint4 aq[2][2], bq[4];
#pragma unroll
            for (int mt = 0; mt < 2; mt++) {
                const float4* ap = Ab + ks * 522 + aoff + wr * 32 + mt * 16;
                aq[mt][0] = *(const uint4*)ap;
                aq[mt][1] = *(const uint4*)(ap + 8);
            }
#pragma unroll
            for (int nt = 0; nt < 4; nt++)
                bq[nt] = *(const uint4*)(Bb + ks * 522 + aoff + wc * 32 + nt * 8);
#pragma unroll
            for (int mt = 0; mt < 2; mt++) {
#pragma unroll
                for (int nt = 0; nt < 4; nt++) {
                    // hi*hi
                    MMA_TF32(acc[mt][nt], aq[mt][0].x, aq[mt][1].x, aq[mt][0].y, aq[mt][1].y,
                             bq[nt].x, bq[nt].y);
                    // hi*lo
                    MMA_TF32(acc[mt][nt], aq[mt][0].x, aq[mt][1].x, aq[mt][0].y, aq[mt][1].y,
                             bq[nt].z, bq[nt].w);
                    // lo*hi
                    MMA_TF32(acc[mt][nt], aq[mt][0].z, aq[mt][1].z, aq[mt][0].w, aq[mt][1].w,
                             bq[nt].x, bq[nt].y);
                }
            }
        }
        if (c + 1 < nC) sts(cur ^ 1, u2, v2);
        __syncthreads();
    }

    // ---------------- epilogue ----------------
    if (EPI == 4) {
#pragma unroll
        for (int mt = 0; mt < 2; mt++) {
#pragma unroll
            for (int h = 0; h < 2; h++) {
                unsigned long long best = ~0ull;
#pragma unroll
                for (int nt = 0; nt < 4; nt++) {
#pragma unroll
                    for (int j = 0; j < 2; j++) {
                        int n = col0 + wc * 32 + nt * 8 + 2 * (lane & 3) + j;
                        float s = bias[n] - 2.f * acc[mt][nt][h * 2 + j];
                        unsigned int ub = __float_as_uint(s);
                        ub = (ub & 0x80000000u) ? ~ub : (ub | 0x80000000u);
                        unsigned long long key = ((unsigned long long)ub << 32) | (unsigned int)n;
                        if (key < best) best = key;
                    }
                }
                unsigned long long o1 = __shfl_xor_sync(0xffffffffu, best, 1);
                if (o1 < best) best = o1;
                unsigned long long o2 = __shfl_xor_sync(0xffffffffu, best, 2);
                if (o2 < best) best = o2;
                if ((lane & 3) == 0)
                    atomicMin(&red[wr * 32 + mt * 16 + (lane >> 2) + 8 * h], best);
            }
        }
        __syncthreads();
        if (tid < 128) atomicMin(&keys[row0 + tid], red[tid]);
        return;
    }

#pragma unroll
    for (int mt = 0; mt < 2; mt++) {
        int r = row0 + wr * 32 + mt * 16 + (lane >> 2);
#pragma unroll
        for (int nt = 0; nt < 4; nt++) {
            int cc0 = col0 + wc * 32 + nt * 8 + 2 * (lane & 3);
            float b0 = bias[cc0], b1 = bias[cc0 + 1];
            float v0 = acc[mt][nt][0] + b0, v1 = acc[mt][nt][1] + b1;
            float v2 = acc[mt][nt][2] + b0, v3 = acc[mt][nt][3] + b1;
            if (EPI == 1) {
                v0 = fmaxf(v0, 0.f); v1 = fmaxf(v1, 0.f);
                v2 = fmaxf(v2, 0.f); v3 = fmaxf(v3, 0.f);
            }
            if (EPI == 2) {
                v0 = gelu_f(v0); v1 = gelu_f(v1);
                v2 = gelu_f(v2); v3 = gelu_f(v3);
            }
            size_t i0 = (size_t)r * N + cc0;
            size_t i1 = (size_t)(r + 8) * N + cc0;
            if (EPI == 3) {
                float2 r0 = *(const float2*)(res + i0);
                float2 r1 = *(const float2*)(res + i1);
                v0 += r0.x; v1 += r0.y; v2 += r1.x; v3 += r1.y;
            }
            *(float2*)(C + i0) = make_float2(v0, v1);
            *(float2*)(C + i1) = make_float2(v2, v3);
        }
    }
}

// ---------------- causal attention (one block per (b,h)) ----------------
__global__ __launch_bounds__(256) void attn_kernel(const float* __restrict__ qkv,
                                                   float* __restrict__ out, int T) {
    extern __shared__ float smx[];
    float* Vs = smx;
    float* Ks = Vs + T * 132;
    float* qs = Ks + T * 129;
    float* ps = qs + 8 * 128;
    int tid = threadIdx.x;
    int bh = blockIdx.x;
    int b = bh >> 2, h = bh & 3;
    const float* base = qkv + (size_t)b * T * 1536 + h * 128;

    for (int idx = tid; idx < T * 128; idx += 256) {
        int j = idx >> 7, d = idx & 127;
        const float* rowp = base + (size_t)j * 1536;
        Ks[j * 129 + d] = rowp[512 + d];
        Vs[j * 132 + d] = rowp[1024 + d];
    }
    __syncthreads();

    int warp = tid >> 5, lane = tid & 31;
    float* qw = qs + warp * 128;
    float* pw = ps + warp * 100;
    const float scale = 0.08838834764831845f;

    for (int i = warp; i < T; i += 8) {
        const float* qrow = base + (size_t)i * 1536;
#pragma unroll
        for (int c = 0; c < 4; c++) qw[lane + 32 * c] = qrow[lane + 32 * c];
        __syncwarp();
        float mx = -1e30f;
        for (int j = lane; j <= i; j += 32) {
            float s = 0.f;
            const float* kr = Ks + j * 129;
#pragma unroll 8
            for (int d = 0; d < 128; d++) s += qw[d] * kr[d];
            s *= scale;
            pw[j] = s;
            if (s > mx) mx = s;
        }
#pragma unroll
        for (int o = 16; o; o >>= 1) mx = fmaxf(mx, __shfl_xor_sync(0xffffffffu, mx, o));
        float sum = 0.f;
        for (int j = lane; j <= i; j += 32) {
            float e = expf(pw[j] - mx);
            pw[j] = e;
            sum += e;
        }
#pragma unroll
        for (int o = 16; o; o >>= 1) sum += __shfl_xor_sync(0xffffffffu, sum, o);
        float inv = 1.f / sum;
        __syncwarp();
        float4 acc = make_float4(0.f, 0.f, 0.f, 0.f);
        for (int j = 0; j <= i; j++) {
            float p = pw[j];
            float4 v = *(const float4*)(Vs + j * 132 + lane * 4);
            acc.x += p * v.x; acc.y += p * v.y; acc.z += p * v.z; acc.w += p * v.w;
        }
        acc.x *= inv; acc.y *= inv; acc.z *= inv; acc.w *= inv;
        *(float4*)(out + (size_t)(b * T + i) * 512 + h * 128 + lane * 4) = acc;
        __syncwarp();
    }
}

// ---------------- layernorm ----------------
__global__ __launch_bounds__(128) void ln_k(const float* __restrict__ in,
                                            const float* __restrict__ g,
                                            const float* __restrict__ bb,
                                            float* __restrict__ out) {
    __shared__ float red[4];
    int row = blockIdx.x, tid = threadIdx.x;
    const float4 x = *(const float4*)(in + (size_t)row * 512 + tid * 4);
    float s = x.x + x.y + x.z + x.w;
#pragma unroll
    for (int o = 16; o; o >>= 1) s += __shfl_xor_sync(0xffffffffu, s, o);
    if ((tid & 31) == 0) red[tid >> 5] = s;
    __syncthreads();
    float mean = (red[0] + red[1] + red[2] + red[3]) * 0.001953125f;
    float a0 = x.x - mean, a1 = x.y - mean, a2 = x.z - mean, a3 = x.w - mean;
    float q = a0 * a0 + a1 * a1 + a2 * a2 + a3 * a3;
#pragma unroll
    for (int o = 16; o; o >>= 1) q += __shfl_xor_sync(0xffffffffu, q, o);
    __syncthreads();
    if ((tid & 31) == 0) red[tid >> 5] = q;
    __syncthreads();
    float var = (red[0] + red[1] + red[2] + red[3]) * 0.001953125f;
    float rs = rsqrtf(var + 1e-5f);
    float4 gv = *(const float4*)(g + tid * 4);
    float4 bv = *(const float4*)(bb + tid * 4);
    float4 o4 = make_float4(a0 * rs * gv.x + bv.x, a1 * rs * gv.y + bv.y,
                            a2 * rs * gv.z + bv.z, a3 * rs * gv.w + bv.w);
    *(float4*)(out + (size_t)row * 512 + tid * 4) = o4;
}

// ---------------- VQ finalize ----------------
__global__ __launch_bounds__(128) void vq_fin(const unsigned long long* __restrict__ keys,
                                              const float* __restrict__ cb,
                                              float* __restrict__ oq,
                                              float* __restrict__ oi) {
    int row = blockIdx.x, tid = threadIdx.x;
    int idx = (int)(keys[row] & 0xffffffffu);
    float4 v = *(const float4*)(cb + (size_t)idx * 512 + tid * 4);
    *(float4*)(oq + (size_t)row * 512 + tid * 4) = v;
    if (tid == 0 && oi) oi[row] = (float)idx;
}

// ---------------- host launch ----------------
extern "C" void kernel_launch(void* const* d_in, const int* in_sizes, int n_in,
                              void* d_out, int out_size) {
    const float* motion = (const float*)d_in[0];
    const float* conv_w = (const float*)d_in[1];
    const float* conv_b = (const float*)d_in[2];
    const float* wqkv   = (const float*)d_in[3];
    const float* bqkv   = (const float*)d_in[4];
    const float* wo     = (const float*)d_in[5];
    const float* bo     = (const float*)d_in[6];
    const float* ln1g   = (const float*)d_in[7];
    const float* ln1b   = (const float*)d_in[8];
    const float* ln2g   = (const float*)d_in[9];
    const float* ln2b   = (const float*)d_in[10];
    const float* w1     = (const float*)d_in[11];
    const float* b1     = (const float*)d_in[12];
    const float* w2     = (const float*)d_in[13];
    const float* b2     = (const float*)d_in[14];
    const float* cbook  = (const float*)d_in[15];

    float *xa, *xb, *at, *tp, *qk, *hd, *qkvT, *woT, *w1T, *w2T, *cvT, *cn;
    unsigned long long* ky;
    cudaGetSymbolAddress((void**)&xa, g_xa);
    cudaGetSymbolAddress((void**)&xb, g_xb);
    cudaGetSymbolAddress((void**)&at, g_at);
    cudaGetSymbolAddress((void**)&tp, g_tp);
    cudaGetSymbolAddress((void**)&qk, g_qk);
    cudaGetSymbolAddress((void**)&hd, g_hd);
    cudaGetSymbolAddress((void**)&qkvT, g_qkvT);
    cudaGetSymbolAddress((void**)&woT, g_woT);
    cudaGetSymbolAddress((void**)&w1T, g_w1T);
    cudaGetSymbolAddress((void**)&w2T, g_w2T);
    cudaGetSymbolAddress((void**)&cvT, g_cvT);
    cudaGetSymbolAddress((void**)&cn, g_cn);
    cudaGetSymbolAddress((void**)&ky, g_key);

    cudaFuncSetAttribute(attn_kernel, cudaFuncAttributeMaxDynamicSharedMemorySize, 120 * 1024);
    cudaFuncSetAttribute(gemm_mma<2, true>,  cudaFuncAttributeMaxDynamicSharedMemorySize, SMEM_MMA);
    cudaFuncSetAttribute(gemm_mma<0, false>, cudaFuncAttributeMaxDynamicSharedMemorySize, SMEM_MMA);
    cudaFuncSetAttribute(gemm_mma<3, false>, cudaFuncAttributeMaxDynamicSharedMemorySize, SMEM_MMA);
    cudaFuncSetAttribute(gemm_mma<1, false>, cudaFuncAttributeMaxDynamicSharedMemorySize, SMEM_MMA);
    cudaFuncSetAttribute(gemm_mma<4, false>, cudaFuncAttributeMaxDynamicSharedMemorySize, SMEM_MMA);

    // weight prep: transpose to [N, K]
    tr_conv<<<(2 * 512 * 1536 + 255) / 256, 256>>>(conv_w, cvT);
    for (int l = 0; l < 2; l++) {
        tr_w<<<dim3(1536 / 32, 512 / 32), dim3(32, 8)>>>(wqkv + (size_t)l * 512 * 1536, qkvT + (size_t)l * 1536 * 512, 512, 1536);
        tr_w<<<dim3(512 / 32, 512 / 32), dim3(32, 8)>>>(wo + (size_t)l * 512 * 512, woT + (size_t)l * 512 * 512, 512, 512);
        tr_w<<<dim3(1024 / 32, 512 / 32), dim3(32, 8)>>>(w1 + (size_t)l * 512 * 1024, w1T + (size_t)l * 1024 * 512, 512, 1024);
        tr_w<<<dim3(512 / 32, 1024 / 32), dim3(32, 8)>>>(w2 + (size_t)l * 1024 * 512, w2T + (size_t)l * 512 * 1024, 1024, 512);
    }
    cnorm_k<<<8192 / 8, 256>>>(cbook, cn);
    key_init<<<(12544 + 255) / 256, 256>>>(ky);

    const float* px = motion;
    int Tin = 196;
    float* bufs[2] = {xa, xb};
    for (int l = 0; l < 2; l++) {
        int Tout = Tin >> 1;
        int M = 256 * Tout;
        float* cx = bufs[l];
        // conv (implicit gather, Kd=1536) + bias + exact GELU
        gemm_mma<2, true><<<dim3(4, M / 128), 512, SMEM_MMA>>>(
            px, cvT + (size_t)l * 512 * 1536, conv_b + l * 512, nullptr, cx, nullptr,
            M, 512, 1536, Tin, Tout);
        // QKV projection
        gemm_mma<0, false><<<dim3(12, M / 128), 512, SMEM_MMA>>>(
            cx, qkvT + (size_t)l * 1536 * 512, bqkv + l * 1536, nullptr, qk, nullptr,
            M, 1536, 512, 0, 0);
        // attention
        size_t smem = (size_t)(Tout * 132 + Tout * 129 + 8 * 128 + 8 * 100) * 4;
        attn_kernel<<<256 * 4, 256, smem>>>(qk, at, Tout);
        // out proj + residual
        gemm_mma<3, false><<<dim3(4, M / 128), 512, SMEM_MMA>>>(
            at, woT + (size_t)l * 512 * 512, bo + l * 512, cx, tp, nullptr,
            M, 512, 512, 0, 0);
        ln_k<<<M, 128>>>(tp, ln1g + l * 512, ln1b + l * 512, cx);
        // FFN
        gemm_mma<1, false><<<dim3(8, M / 128), 512, SMEM_MMA>>>(
            cx, w1T + (size_t)l * 1024 * 512, b1 + l * 1024, nullptr, hd, nullptr,
            M, 1024, 512, 0, 0);
        gemm_mma<3, false><<<dim3(4, M / 128), 512, SMEM_MMA>>>(
            hd, w2T + (size_t)l * 512 * 1024, b2 + l * 512, cx, tp, nullptr,
            M, 512, 1024, 0, 0);
        ln_k<<<M, 128>>>(tp, ln2g + l * 512, ln2b + l * 512, cx);
        px = cx;
        Tin = Tout;
    }

    // VQ: 3xTF32 scores + fused per-row argmin
    gemm_mma<4, false><<<dim3(64, 98), 512, SMEM_MMA>>>(
        px, cbook, cn, nullptr, nullptr, ky, 12544, 8192, 512, 0, 0);

    float* out = (float*)d_out;
    float* oidx = (out_size >= 12544 * 512 + 12544) ? out + (size_t)12544 * 512 : nullptr;
    vq_fin<<<12544, 128>>>(ky, cbook, out, oidx);
}